// round 3
// baseline (speedup 1.0000x reference)
#include <cuda_runtime.h>
#include <math.h>

// ---------------------------------------------------------------------------
// MoE grouped MLP: T=4096 tokens, H=2048 hidden, I=1408 intermediate,
// E=8 experts, top-K=2.
//   rows = K*T = 8192 expanded rows, grouped by expert.
//   act  = silu(x @ gate_w[e]) * (x @ up_w[e])     [8192, I]
//   out[t] += prob * (act_row @ down_w[e])         [T, H]
// Round-1 baseline: fp32 SIMT tiled GEMMs + device-side permutation.
// ---------------------------------------------------------------------------

#define T_TOK 4096
#define H_DIM 2048
#define I_DIM 1408
#define N_EXP 8
#define TOPK  2
#define R_ROWS (T_TOK * TOPK)       // 8192

#define BM 128
#define BN 64
#define BK 16
#define MAX_TILES (R_ROWS / BM + N_EXP)   // 72 worst case

// ---- device-global scratch (no allocations allowed) ----
__device__ int   g_counts[N_EXP];
__device__ int   g_cursor[N_EXP];
__device__ int   g_tile_e[MAX_TILES];
__device__ int   g_tile_row0[MAX_TILES];
__device__ int   g_tile_rows[MAX_TILES];
__device__ int   g_num_tiles;
__device__ int   g_row_t[R_ROWS];         // source token per sorted row
__device__ float g_row_p[R_ROWS];         // router prob per sorted row
__device__ float g_act[R_ROWS * I_DIM];   // 46 MB intermediate activations

// ---------------------------------------------------------------------------
__global__ void k_zero_counts() {
    if (threadIdx.x < N_EXP) g_counts[threadIdx.x] = 0;
}

__global__ void k_hist(const int* __restrict__ sel) {
    int f = blockIdx.x * blockDim.x + threadIdx.x;
    if (f < R_ROWS) {
        int t = f % T_TOK;
        int k = f / T_TOK;
        atomicAdd(&g_counts[sel[t * TOPK + k]], 1);
    }
}

__global__ void k_prep() {
    // single thread: prefix sum over 8 experts + build ragged tile table
    int off = 0, nt = 0;
    for (int e = 0; e < N_EXP; ++e) {
        int c = g_counts[e];
        g_cursor[e] = off;
        for (int r0 = 0; r0 < c; r0 += BM) {
            g_tile_e[nt]    = e;
            g_tile_row0[nt] = off + r0;
            g_tile_rows[nt] = min(BM, c - r0);
            ++nt;
        }
        off += c;
    }
    g_num_tiles = nt;
}

__global__ void k_scatter(const int* __restrict__ sel,
                          const float* __restrict__ rw) {
    int f = blockIdx.x * blockDim.x + threadIdx.x;
    if (f < R_ROWS) {
        int t = f % T_TOK;
        int k = f / T_TOK;
        int e = sel[t * TOPK + k];
        int d = atomicAdd(&g_cursor[e], 1);
        g_row_t[d] = t;
        g_row_p[d] = rw[t * TOPK + k];
    }
}

__global__ void k_zero_out(float4* __restrict__ out, int n4) {
    int i = blockIdx.x * blockDim.x + threadIdx.x;
    if (i < n4) out[i] = make_float4(0.f, 0.f, 0.f, 0.f);
}

// ---------------------------------------------------------------------------
// GEMM1: fused gate+up.  C_g = A @ gate_w[e], C_u = A @ up_w[e],
// act = silu(C_g) * C_u.  A rows gathered from hidden_states via g_row_t.
// Block: BM x BN tile, 256 threads, 8x4 microtile per thread.
// ---------------------------------------------------------------------------
__global__ __launch_bounds__(256, 2)
void k_gemm1(const float* __restrict__ hid,
             const float* __restrict__ gw,
             const float* __restrict__ uw) {
    const int tile = blockIdx.x;
    if (tile >= g_num_tiles) return;
    const int e    = g_tile_e[tile];
    const int row0 = g_tile_row0[tile];
    const int rows = g_tile_rows[tile];
    const int n0   = blockIdx.y * BN;

    __shared__ float As[BK][BM];
    __shared__ float Bg[BK][BN];
    __shared__ float Bu[BK][BN];

    const int tid   = threadIdx.x;
    const int tx    = tid & 15;
    const int ty    = tid >> 4;
    const int rbase = ty * 8;
    const int cbase = tx * 4;

    const float* gwe = gw + (size_t)e * H_DIM * I_DIM;
    const float* uwe = uw + (size_t)e * H_DIM * I_DIM;

    // A-load mapping: each thread loads 2 float4s of the 128x16 A tile
    const int aidx  = tid * 2;
    const int ar0   = aidx >> 2,       akq0 = aidx & 3;
    const int ar1   = (aidx + 1) >> 2, akq1 = (aidx + 1) & 3;
    const int at0   = (ar0 < rows) ? g_row_t[row0 + ar0] : -1;
    const int at1   = (ar1 < rows) ? g_row_t[row0 + ar1] : -1;

    // B-load mapping: one float4 per thread per B matrix
    const int bkk = tid >> 4;
    const int bn  = (tid & 15) * 4;

    float accg[8][4], accu[8][4];
    #pragma unroll
    for (int i = 0; i < 8; ++i)
        #pragma unroll
        for (int j = 0; j < 4; ++j) { accg[i][j] = 0.f; accu[i][j] = 0.f; }

    for (int k0 = 0; k0 < H_DIM; k0 += BK) {
        float4 va = (at0 >= 0)
            ? *(const float4*)&hid[(size_t)at0 * H_DIM + k0 + akq0 * 4]
            : make_float4(0.f, 0.f, 0.f, 0.f);
        float4 vb = (at1 >= 0)
            ? *(const float4*)&hid[(size_t)at1 * H_DIM + k0 + akq1 * 4]
            : make_float4(0.f, 0.f, 0.f, 0.f);
        float4 vg = *(const float4*)&gwe[(size_t)(k0 + bkk) * I_DIM + n0 + bn];
        float4 vu = *(const float4*)&uwe[(size_t)(k0 + bkk) * I_DIM + n0 + bn];

        __syncthreads();   // previous iteration's compute done
        As[akq0 * 4 + 0][ar0] = va.x;
        As[akq0 * 4 + 1][ar0] = va.y;
        As[akq0 * 4 + 2][ar0] = va.z;
        As[akq0 * 4 + 3][ar0] = va.w;
        As[akq1 * 4 + 0][ar1] = vb.x;
        As[akq1 * 4 + 1][ar1] = vb.y;
        As[akq1 * 4 + 2][ar1] = vb.z;
        As[akq1 * 4 + 3][ar1] = vb.w;
        *(float4*)&Bg[bkk][bn] = vg;
        *(float4*)&Bu[bkk][bn] = vu;
        __syncthreads();

        #pragma unroll
        for (int kk = 0; kk < BK; ++kk) {
            float4 a0 = *(const float4*)&As[kk][rbase];
            float4 a1 = *(const float4*)&As[kk][rbase + 4];
            float4 g4 = *(const float4*)&Bg[kk][cbase];
            float4 u4 = *(const float4*)&Bu[kk][cbase];
            float a[8]  = {a0.x, a0.y, a0.z, a0.w, a1.x, a1.y, a1.z, a1.w};
            float gv[4] = {g4.x, g4.y, g4.z, g4.w};
            float uv[4] = {u4.x, u4.y, u4.z, u4.w};
            #pragma unroll
            for (int i = 0; i < 8; ++i)
                #pragma unroll
                for (int j = 0; j < 4; ++j) {
                    accg[i][j] += a[i] * gv[j];
                    accu[i][j] += a[i] * uv[j];
                }
        }
    }

    // epilogue: act = silu(g) * u
    #pragma unroll
    for (int i = 0; i < 8; ++i) {
        int r = rbase + i;
        if (r < rows) {
            float* dst = &g_act[(size_t)(row0 + r) * I_DIM + n0 + cbase];
            float4 o;
            float g, u;
            g = accg[i][0]; u = accu[i][0]; o.x = (g / (1.f + __expf(-g))) * u;
            g = accg[i][1]; u = accu[i][1]; o.y = (g / (1.f + __expf(-g))) * u;
            g = accg[i][2]; u = accu[i][2]; o.z = (g / (1.f + __expf(-g))) * u;
            g = accg[i][3]; u = accu[i][3]; o.w = (g / (1.f + __expf(-g))) * u;
            *(float4*)dst = o;
        }
    }
}

// ---------------------------------------------------------------------------
// GEMM2: down projection + weighted scatter-add into out.
//   C = act_rows @ down_w[e];  out[t, :] += prob * C_row
// ---------------------------------------------------------------------------
__global__ __launch_bounds__(256, 2)
void k_gemm2(const float* __restrict__ dw,
             float* __restrict__ out) {
    const int tile = blockIdx.x;
    if (tile >= g_num_tiles) return;
    const int e    = g_tile_e[tile];
    const int row0 = g_tile_row0[tile];
    const int rows = g_tile_rows[tile];
    const int n0   = blockIdx.y * BN;

    __shared__ float As[BK][BM];
    __shared__ float Bs[BK][BN];

    const int tid   = threadIdx.x;
    const int tx    = tid & 15;
    const int ty    = tid >> 4;
    const int rbase = ty * 8;
    const int cbase = tx * 4;

    const float* dwe = dw + (size_t)e * I_DIM * H_DIM;

    const int aidx = tid * 2;
    const int ar0  = aidx >> 2,       akq0 = aidx & 3;
    const int ar1  = (aidx + 1) >> 2, akq1 = (aidx + 1) & 3;
    const bool av0 = (ar0 < rows);
    const bool av1 = (ar1 < rows);

    const int bkk = tid >> 4;
    const int bn  = (tid & 15) * 4;

    float acc[8][4];
    #pragma unroll
    for (int i = 0; i < 8; ++i)
        #pragma unroll
        for (int j = 0; j < 4; ++j) acc[i][j] = 0.f;

    for (int k0 = 0; k0 < I_DIM; k0 += BK) {
        float4 va = av0
            ? *(const float4*)&g_act[(size_t)(row0 + ar0) * I_DIM + k0 + akq0 * 4]
            : make_float4(0.f, 0.f, 0.f, 0.f);
        float4 vb = av1
            ? *(const float4*)&g_act[(size_t)(row0 + ar1) * I_DIM + k0 + akq1 * 4]
            : make_float4(0.f, 0.f, 0.f, 0.f);
        float4 vB = *(const float4*)&dwe[(size_t)(k0 + bkk) * H_DIM + n0 + bn];

        __syncthreads();
        As[akq0 * 4 + 0][ar0] = va.x;
        As[akq0 * 4 + 1][ar0] = va.y;
        As[akq0 * 4 + 2][ar0] = va.z;
        As[akq0 * 4 + 3][ar0] = va.w;
        As[akq1 * 4 + 0][ar1] = vb.x;
        As[akq1 * 4 + 1][ar1] = vb.y;
        As[akq1 * 4 + 2][ar1] = vb.z;
        As[akq1 * 4 + 3][ar1] = vb.w;
        *(float4*)&Bs[bkk][bn] = vB;
        __syncthreads();

        #pragma unroll
        for (int kk = 0; kk < BK; ++kk) {
            float4 a0 = *(const float4*)&As[kk][rbase];
            float4 a1 = *(const float4*)&As[kk][rbase + 4];
            float4 b4 = *(const float4*)&Bs[kk][cbase];
            float a[8]  = {a0.x, a0.y, a0.z, a0.w, a1.x, a1.y, a1.z, a1.w};
            float bv[4] = {b4.x, b4.y, b4.z, b4.w};
            #pragma unroll
            for (int i = 0; i < 8; ++i)
                #pragma unroll
                for (int j = 0; j < 4; ++j)
                    acc[i][j] += a[i] * bv[j];
        }
    }

    // epilogue: weighted scatter-add (each out element receives exactly K=2 adds)
    #pragma unroll
    for (int i = 0; i < 8; ++i) {
        int r = rbase + i;
        if (r < rows) {
            float p = g_row_p[row0 + r];
            int   t = g_row_t[row0 + r];
            float* dst = &out[(size_t)t * H_DIM + n0 + cbase];
            #pragma unroll
            for (int j = 0; j < 4; ++j)
                atomicAdd(&dst[j], acc[i][j] * p);
        }
    }
}

// ---------------------------------------------------------------------------
extern "C" void kernel_launch(void* const* d_in, const int* in_sizes, int n_in,
                              void* d_out, int out_size) {
    const float* hid = (const float*)d_in[0];   // [T, H]
    const float* rw  = (const float*)d_in[1];   // [T, K]
    const int*   sel = (const int*)  d_in[2];   // [T, K]
    const float* gw  = (const float*)d_in[3];   // [E, H, I]
    const float* uw  = (const float*)d_in[4];   // [E, H, I]
    const float* dw  = (const float*)d_in[5];   // [E, I, H]
    float* out = (float*)d_out;                 // [T, H]

    k_zero_counts<<<1, 32>>>();
    k_hist<<<R_ROWS / 256, 256>>>(sel);
    k_prep<<<1, 1>>>();
    k_scatter<<<R_ROWS / 256, 256>>>(sel, rw);

    int n4 = (T_TOK * H_DIM) / 4;
    k_zero_out<<<n4 / 256, 256>>>((float4*)out, n4);

    dim3 g1(MAX_TILES, I_DIM / BN);   // 72 x 22
    k_gemm1<<<g1, 256>>>(hid, gw, uw);

    dim3 g2(MAX_TILES, H_DIM / BN);   // 72 x 32
    k_gemm2<<<g2, 256>>>(dw, out);
}

// round 4
// speedup vs baseline: 1.0572x; 1.0572x over previous
#include <cuda_runtime.h>
#include <math.h>

// ---------------------------------------------------------------------------
// MoE grouped MLP: T=4096 tokens, H=2048 hidden, I=1408 intermediate,
// E=8 experts, top-K=2.
//   rows = K*T = 8192 expanded rows, grouped by expert.
//   act  = silu(x @ gate_w[e]) * (x @ up_w[e])     [8192, I]
//   out[t] += prob * (act_row @ down_w[e])         [T, H]
// Round-1 baseline: fp32 SIMT tiled GEMMs + device-side permutation.
// ---------------------------------------------------------------------------

#define T_TOK 4096
#define H_DIM 2048
#define I_DIM 1408
#define N_EXP 8
#define TOPK  2
#define R_ROWS (T_TOK * TOPK)       // 8192

#define BM 128
#define BN 64
#define BK 16
#define MAX_TILES (R_ROWS / BM + N_EXP)   // 72 worst case

// ---- device-global scratch (no allocations allowed) ----
__device__ int   g_counts[N_EXP];
__device__ int   g_cursor[N_EXP];
__device__ int   g_tile_e[MAX_TILES];
__device__ int   g_tile_row0[MAX_TILES];
__device__ int   g_tile_rows[MAX_TILES];
__device__ int   g_num_tiles;
__device__ int   g_row_t[R_ROWS];         // source token per sorted row
__device__ float g_row_p[R_ROWS];         // router prob per sorted row
__device__ float g_act[R_ROWS * I_DIM];   // 46 MB intermediate activations

// ---------------------------------------------------------------------------
__global__ void k_zero_counts() {
    if (threadIdx.x < N_EXP) g_counts[threadIdx.x] = 0;
}

__global__ void k_hist(const int* __restrict__ sel) {
    int f = blockIdx.x * blockDim.x + threadIdx.x;
    if (f < R_ROWS) {
        int t = f % T_TOK;
        int k = f / T_TOK;
        atomicAdd(&g_counts[sel[t * TOPK + k]], 1);
    }
}

__global__ void k_prep() {
    // single thread: prefix sum over 8 experts + build ragged tile table
    int off = 0, nt = 0;
    for (int e = 0; e < N_EXP; ++e) {
        int c = g_counts[e];
        g_cursor[e] = off;
        for (int r0 = 0; r0 < c; r0 += BM) {
            g_tile_e[nt]    = e;
            g_tile_row0[nt] = off + r0;
            g_tile_rows[nt] = min(BM, c - r0);
            ++nt;
        }
        off += c;
    }
    g_num_tiles = nt;
}

__global__ void k_scatter(const int* __restrict__ sel,
                          const float* __restrict__ rw) {
    int f = blockIdx.x * blockDim.x + threadIdx.x;
    if (f < R_ROWS) {
        int t = f % T_TOK;
        int k = f / T_TOK;
        int e = sel[t * TOPK + k];
        int d = atomicAdd(&g_cursor[e], 1);
        g_row_t[d] = t;
        g_row_p[d] = rw[t * TOPK + k];
    }
}

__global__ void k_zero_out(float4* __restrict__ out, int n4) {
    int i = blockIdx.x * blockDim.x + threadIdx.x;
    if (i < n4) out[i] = make_float4(0.f, 0.f, 0.f, 0.f);
}

// ---------------------------------------------------------------------------
// GEMM1: fused gate+up.  C_g = A @ gate_w[e], C_u = A @ up_w[e],
// act = silu(C_g) * C_u.  A rows gathered from hidden_states via g_row_t.
// Block: BM x BN tile, 256 threads, 8x4 microtile per thread.
// ---------------------------------------------------------------------------
__global__ __launch_bounds__(256, 2)
void k_gemm1(const float* __restrict__ hid,
             const float* __restrict__ gw,
             const float* __restrict__ uw) {
    const int tile = blockIdx.x;
    if (tile >= g_num_tiles) return;
    const int e    = g_tile_e[tile];
    const int row0 = g_tile_row0[tile];
    const int rows = g_tile_rows[tile];
    const int n0   = blockIdx.y * BN;

    __shared__ float As[BK][BM];
    __shared__ float Bg[BK][BN];
    __shared__ float Bu[BK][BN];

    const int tid   = threadIdx.x;
    const int tx    = tid & 15;
    const int ty    = tid >> 4;
    const int rbase = ty * 8;
    const int cbase = tx * 4;

    const float* gwe = gw + (size_t)e * H_DIM * I_DIM;
    const float* uwe = uw + (size_t)e * H_DIM * I_DIM;

    // A-load mapping: each thread loads 2 float4s of the 128x16 A tile
    const int aidx  = tid * 2;
    const int ar0   = aidx >> 2,       akq0 = aidx & 3;
    const int ar1   = (aidx + 1) >> 2, akq1 = (aidx + 1) & 3;
    const int at0   = (ar0 < rows) ? g_row_t[row0 + ar0] : -1;
    const int at1   = (ar1 < rows) ? g_row_t[row0 + ar1] : -1;

    // B-load mapping: one float4 per thread per B matrix
    const int bkk = tid >> 4;
    const int bn  = (tid & 15) * 4;

    float accg[8][4], accu[8][4];
    #pragma unroll
    for (int i = 0; i < 8; ++i)
        #pragma unroll
        for (int j = 0; j < 4; ++j) { accg[i][j] = 0.f; accu[i][j] = 0.f; }

    for (int k0 = 0; k0 < H_DIM; k0 += BK) {
        float4 va = (at0 >= 0)
            ? *(const float4*)&hid[(size_t)at0 * H_DIM + k0 + akq0 * 4]
            : make_float4(0.f, 0.f, 0.f, 0.f);
        float4 vb = (at1 >= 0)
            ? *(const float4*)&hid[(size_t)at1 * H_DIM + k0 + akq1 * 4]
            : make_float4(0.f, 0.f, 0.f, 0.f);
        float4 vg = *(const float4*)&gwe[(size_t)(k0 + bkk) * I_DIM + n0 + bn];
        float4 vu = *(const float4*)&uwe[(size_t)(k0 + bkk) * I_DIM + n0 + bn];

        __syncthreads();   // previous iteration's compute done
        As[akq0 * 4 + 0][ar0] = va.x;
        As[akq0 * 4 + 1][ar0] = va.y;
        As[akq0 * 4 + 2][ar0] = va.z;
        As[akq0 * 4 + 3][ar0] = va.w;
        As[akq1 * 4 + 0][ar1] = vb.x;
        As[akq1 * 4 + 1][ar1] = vb.y;
        As[akq1 * 4 + 2][ar1] = vb.z;
        As[akq1 * 4 + 3][ar1] = vb.w;
        *(float4*)&Bg[bkk][bn] = vg;
        *(float4*)&Bu[bkk][bn] = vu;
        __syncthreads();

        #pragma unroll
        for (int kk = 0; kk < BK; ++kk) {
            float4 a0 = *(const float4*)&As[kk][rbase];
            float4 a1 = *(const float4*)&As[kk][rbase + 4];
            float4 g4 = *(const float4*)&Bg[kk][cbase];
            float4 u4 = *(const float4*)&Bu[kk][cbase];
            float a[8]  = {a0.x, a0.y, a0.z, a0.w, a1.x, a1.y, a1.z, a1.w};
            float gv[4] = {g4.x, g4.y, g4.z, g4.w};
            float uv[4] = {u4.x, u4.y, u4.z, u4.w};
            #pragma unroll
            for (int i = 0; i < 8; ++i)
                #pragma unroll
                for (int j = 0; j < 4; ++j) {
                    accg[i][j] += a[i] * gv[j];
                    accu[i][j] += a[i] * uv[j];
                }
        }
    }

    // epilogue: act = silu(g) * u
    #pragma unroll
    for (int i = 0; i < 8; ++i) {
        int r = rbase + i;
        if (r < rows) {
            float* dst = &g_act[(size_t)(row0 + r) * I_DIM + n0 + cbase];
            float4 o;
            float g, u;
            g = accg[i][0]; u = accu[i][0]; o.x = (g / (1.f + __expf(-g))) * u;
            g = accg[i][1]; u = accu[i][1]; o.y = (g / (1.f + __expf(-g))) * u;
            g = accg[i][2]; u = accu[i][2]; o.z = (g / (1.f + __expf(-g))) * u;
            g = accg[i][3]; u = accu[i][3]; o.w = (g / (1.f + __expf(-g))) * u;
            *(float4*)dst = o;
        }
    }
}

// ---------------------------------------------------------------------------
// GEMM2: down projection + weighted scatter-add into out.
//   C = act_rows @ down_w[e];  out[t, :] += prob * C_row
// ---------------------------------------------------------------------------
__global__ __launch_bounds__(256, 2)
void k_gemm2(const float* __restrict__ dw,
             float* __restrict__ out) {
    const int tile = blockIdx.x;
    if (tile >= g_num_tiles) return;
    const int e    = g_tile_e[tile];
    const int row0 = g_tile_row0[tile];
    const int rows = g_tile_rows[tile];
    const int n0   = blockIdx.y * BN;

    __shared__ float As[BK][BM];
    __shared__ float Bs[BK][BN];

    const int tid   = threadIdx.x;
    const int tx    = tid & 15;
    const int ty    = tid >> 4;
    const int rbase = ty * 8;
    const int cbase = tx * 4;

    const float* dwe = dw + (size_t)e * I_DIM * H_DIM;

    const int aidx = tid * 2;
    const int ar0  = aidx >> 2,       akq0 = aidx & 3;
    const int ar1  = (aidx + 1) >> 2, akq1 = (aidx + 1) & 3;
    const bool av0 = (ar0 < rows);
    const bool av1 = (ar1 < rows);

    const int bkk = tid >> 4;
    const int bn  = (tid & 15) * 4;

    float acc[8][4];
    #pragma unroll
    for (int i = 0; i < 8; ++i)
        #pragma unroll
        for (int j = 0; j < 4; ++j) acc[i][j] = 0.f;

    for (int k0 = 0; k0 < I_DIM; k0 += BK) {
        float4 va = av0
            ? *(const float4*)&g_act[(size_t)(row0 + ar0) * I_DIM + k0 + akq0 * 4]
            : make_float4(0.f, 0.f, 0.f, 0.f);
        float4 vb = av1
            ? *(const float4*)&g_act[(size_t)(row0 + ar1) * I_DIM + k0 + akq1 * 4]
            : make_float4(0.f, 0.f, 0.f, 0.f);
        float4 vB = *(const float4*)&dwe[(size_t)(k0 + bkk) * H_DIM + n0 + bn];

        __syncthreads();
        As[akq0 * 4 + 0][ar0] = va.x;
        As[akq0 * 4 + 1][ar0] = va.y;
        As[akq0 * 4 + 2][ar0] = va.z;
        As[akq0 * 4 + 3][ar0] = va.w;
        As[akq1 * 4 + 0][ar1] = vb.x;
        As[akq1 * 4 + 1][ar1] = vb.y;
        As[akq1 * 4 + 2][ar1] = vb.z;
        As[akq1 * 4 + 3][ar1] = vb.w;
        *(float4*)&Bs[bkk][bn] = vB;
        __syncthreads();

        #pragma unroll
        for (int kk = 0; kk < BK; ++kk) {
            float4 a0 = *(const float4*)&As[kk][rbase];
            float4 a1 = *(const float4*)&As[kk][rbase + 4];
            float4 b4 = *(const float4*)&Bs[kk][cbase];
            float a[8]  = {a0.x, a0.y, a0.z, a0.w, a1.x, a1.y, a1.z, a1.w};
            float bv[4] = {b4.x, b4.y, b4.z, b4.w};
            #pragma unroll
            for (int i = 0; i < 8; ++i)
                #pragma unroll
                for (int j = 0; j < 4; ++j)
                    acc[i][j] += a[i] * bv[j];
        }
    }

    // epilogue: weighted scatter-add (each out element receives exactly K=2 adds)
    #pragma unroll
    for (int i = 0; i < 8; ++i) {
        int r = rbase + i;
        if (r < rows) {
            float p = g_row_p[row0 + r];
            int   t = g_row_t[row0 + r];
            float* dst = &out[(size_t)t * H_DIM + n0 + cbase];
            #pragma unroll
            for (int j = 0; j < 4; ++j)
                atomicAdd(&dst[j], acc[i][j] * p);
        }
    }
}

// ---------------------------------------------------------------------------
extern "C" void kernel_launch(void* const* d_in, const int* in_sizes, int n_in,
                              void* d_out, int out_size) {
    const float* hid = (const float*)d_in[0];   // [T, H]
    const float* rw  = (const float*)d_in[1];   // [T, K]
    const int*   sel = (const int*)  d_in[2];   // [T, K]
    const float* gw  = (const float*)d_in[3];   // [E, H, I]
    const float* uw  = (const float*)d_in[4];   // [E, H, I]
    const float* dw  = (const float*)d_in[5];   // [E, I, H]
    float* out = (float*)d_out;                 // [T, H]

    k_zero_counts<<<1, 32>>>();
    k_hist<<<R_ROWS / 256, 256>>>(sel);
    k_prep<<<1, 1>>>();
    k_scatter<<<R_ROWS / 256, 256>>>(sel, rw);

    int n4 = (T_TOK * H_DIM) / 4;
    k_zero_out<<<n4 / 256, 256>>>((float4*)out, n4);

    dim3 g1(MAX_TILES, I_DIM / BN);   // 72 x 22
    k_gemm1<<<g1, 256>>>(hid, gw, uw);

    dim3 g2(MAX_TILES, H_DIM / BN);   // 72 x 32
    k_gemm2<<<g2, 256>>>(dw, out);
}

// round 6
// speedup vs baseline: 2.5244x; 2.3878x over previous
#include <cuda_runtime.h>
#include <math.h>
#include <stdint.h>

// ---------------------------------------------------------------------------
// MoE grouped MLP via mma.sync tf32 (base compute_103 target — no tcgen05).
// T=4096 H=2048 I=1408 E=8 K=2; rows = 8192.
// ---------------------------------------------------------------------------
#define T_TOK 4096
#define H_DIM 2048
#define I_DIM 1408
#define N_EXP 8
#define TOPK  2
#define R_ROWS (T_TOK * TOPK)
#define BM 128
#define MAX_TILES (R_ROWS / BM + N_EXP)   // 72

#define BN 64
#define BK 16
#define STAGES 3
#define NK1 (H_DIM / BK)                   // 128
#define NK2 (I_DIM / BK)                   // 88

#define A_STRIDE 20                        // conflict-free padded stride (floats)
#define AS_FLOATS (BM * A_STRIDE)          // 2560
#define BS_FLOATS (BN * A_STRIDE)          // 1280
#define G1_SMEM ((STAGES * (AS_FLOATS + 2 * BS_FLOATS)) * 4)   // 61440 B
#define G2_SMEM ((STAGES * (AS_FLOATS + BS_FLOATS)) * 4)       // 46080 B

#define XP_ROWS  (R_ROWS + 128)            // pad so ragged tiles never read OOB
#define ACT_ROWS (R_ROWS + 128)

// ---- device-global scratch ----
__device__ int   g_counts[N_EXP];
__device__ int   g_cursor[N_EXP];
__device__ int   g_tile_e[MAX_TILES];
__device__ int   g_tile_row0[MAX_TILES];
__device__ int   g_tile_rows[MAX_TILES];
__device__ int   g_num_tiles;
__device__ int   g_row_t[R_ROWS];
__device__ float g_row_p[R_ROWS];
__device__ float g_xp[(size_t)XP_ROWS * H_DIM];             // tf32 permuted input
__device__ float g_act[(size_t)ACT_ROWS * I_DIM];           // tf32 activations
__device__ float g_gate_t[(size_t)N_EXP * I_DIM * H_DIM];   // [E][I][H]  (B col-major)
__device__ float g_up_t  [(size_t)N_EXP * I_DIM * H_DIM];
__device__ float g_down_t[(size_t)N_EXP * H_DIM * I_DIM];   // [E][H][I]

// ---------------------------------------------------------------------------
// helpers
// ---------------------------------------------------------------------------
__device__ __forceinline__ float to_tf32(float x) {
    uint32_t t;
    asm("cvt.rna.tf32.f32 %0, %1;" : "=r"(t) : "f"(x));
    return __uint_as_float(t);
}
__device__ __forceinline__ void cp16(void* dst, const void* src) {
    uint32_t d = (uint32_t)__cvta_generic_to_shared(dst);
    asm volatile("cp.async.cg.shared.global [%0], [%1], 16;" :: "r"(d), "l"(src) : "memory");
}
#define CP_COMMIT() asm volatile("cp.async.commit_group;" ::: "memory")
#define CP_WAIT1()  asm volatile("cp.async.wait_group 1;" ::: "memory")

// D += A(16x8,row) * B(8x8,col), tf32 inputs, f32 accum
#define MMA_TF32(d, a, b0, b1)                                            \
    asm volatile("mma.sync.aligned.m16n8k8.row.col.f32.tf32.tf32.f32 "    \
        "{%0,%1,%2,%3}, {%4,%5,%6,%7}, {%8,%9}, {%0,%1,%2,%3};"           \
        : "+f"((d)[0]), "+f"((d)[1]), "+f"((d)[2]), "+f"((d)[3])          \
        : "r"((a)[0]), "r"((a)[1]), "r"((a)[2]), "r"((a)[3]),             \
          "r"(b0), "r"(b1))

// ---------------------------------------------------------------------------
// prep kernels
// ---------------------------------------------------------------------------
__global__ void k_zero_counts() { if (threadIdx.x < N_EXP) g_counts[threadIdx.x] = 0; }

__global__ void k_hist(const int* __restrict__ sel) {
    int f = blockIdx.x * blockDim.x + threadIdx.x;
    if (f < R_ROWS) {
        int t = f % T_TOK, k = f / T_TOK;
        atomicAdd(&g_counts[sel[t * TOPK + k]], 1);
    }
}

__global__ void k_prep() {
    int off = 0, nt = 0;
    for (int e = 0; e < N_EXP; ++e) {
        int c = g_counts[e];
        g_cursor[e] = off;
        for (int r0 = 0; r0 < c; r0 += BM) {
            g_tile_e[nt] = e; g_tile_row0[nt] = off + r0;
            g_tile_rows[nt] = min(BM, c - r0); ++nt;
        }
        off += c;
    }
    g_num_tiles = nt;
}

__global__ void k_scatter(const int* __restrict__ sel, const float* __restrict__ rw) {
    int f = blockIdx.x * blockDim.x + threadIdx.x;
    if (f < R_ROWS) {
        int t = f % T_TOK, k = f / T_TOK;
        int e = sel[t * TOPK + k];
        int d = atomicAdd(&g_cursor[e], 1);
        g_row_t[d] = t;
        g_row_p[d] = rw[t * TOPK + k];
    }
}

__global__ void k_zero_out(float4* __restrict__ out, int n4) {
    int i = blockIdx.x * blockDim.x + threadIdx.x;
    if (i < n4) out[i] = make_float4(0.f, 0.f, 0.f, 0.f);
}

// gather rows + RNA tf32 convert
__global__ void k_permute(const float* __restrict__ hid) {
    int r = blockIdx.x;
    int t = g_row_t[r];
    const float4* src = (const float4*)(hid + (size_t)t * H_DIM);
    float4* dst = (float4*)(g_xp + (size_t)r * H_DIM);
    for (int i = threadIdx.x; i < H_DIM / 4; i += blockDim.x) {
        float4 v = src[i];
        v.x = to_tf32(v.x); v.y = to_tf32(v.y); v.z = to_tf32(v.z); v.w = to_tf32(v.w);
        dst[i] = v;
    }
}

// transpose + RNA convert: in [R,C] per expert -> out [C,R] per expert
template<int R, int C>
__global__ void k_transpose(const float* __restrict__ in, float* __restrict__ out) {
    __shared__ float tile[32][33];
    int e = blockIdx.z;
    in  += (size_t)e * R * C;
    out += (size_t)e * R * C;
    int c0 = blockIdx.x * 32, r0 = blockIdx.y * 32;
    int x = threadIdx.x, y = threadIdx.y;
    #pragma unroll
    for (int dy = 0; dy < 32; dy += 8)
        tile[y + dy][x] = in[(size_t)(r0 + y + dy) * C + c0 + x];
    __syncthreads();
    #pragma unroll
    for (int dy = 0; dy < 32; dy += 8)
        out[(size_t)(c0 + y + dy) * R + r0 + x] = to_tf32(tile[x][y + dy]);
}

// ---------------------------------------------------------------------------
// GEMM1: act = silu(xp @ gate^T) * (xp @ up^T)    [tiles of 128 x 64]
// 256 threads = 8 warps (4M x 2N), warp tile 32x32, mma m16n8k8 tf32.
// ---------------------------------------------------------------------------
__global__ __launch_bounds__(256, 2)
void k_gemm1_mma(const float* __restrict__ xp,
                 const float* __restrict__ gt,
                 const float* __restrict__ ut) {
    const int tile = blockIdx.x;
    if (tile >= g_num_tiles) return;
    const int e    = g_tile_e[tile];
    const int row0 = g_tile_row0[tile];
    const int rows = g_tile_rows[tile];
    const int n0   = blockIdx.y * BN;

    extern __shared__ float sm[];
    float* As = sm;                            // [S][128][20]
    float* Bg = sm + STAGES * AS_FLOATS;       // [S][64][20]
    float* Bu = Bg + STAGES * BS_FLOATS;

    const int tid  = threadIdx.x;
    const int lane = tid & 31, wid = tid >> 5;
    const int wm = wid & 3, wn = wid >> 2;
    const int lg = lane >> 2, lt = lane & 3;   // groupID, threadInGroup

    const float* arow = xp + (size_t)row0 * H_DIM;
    const float* gte  = gt + ((size_t)e * I_DIM + n0) * H_DIM;
    const float* ute  = ut + ((size_t)e * I_DIM + n0) * H_DIM;

    const int lr  = tid >> 2;         // 0..63
    const int lkq = (tid & 3) * 4;    // 0,4,8,12

    float accg[2][4][4], accu[2][4][4];
    #pragma unroll
    for (int a = 0; a < 2; ++a)
        #pragma unroll
        for (int b = 0; b < 4; ++b)
            #pragma unroll
            for (int c = 0; c < 4; ++c) { accg[a][b][c] = 0.f; accu[a][b][c] = 0.f; }

    #define G1_LOAD(s, ki) do {                                                  \
        int k0_ = (ki) * BK;                                                     \
        float* as_ = As + (s) * AS_FLOATS;                                       \
        float* bg_ = Bg + (s) * BS_FLOATS;                                       \
        float* bu_ = Bu + (s) * BS_FLOATS;                                       \
        cp16(&as_[lr * A_STRIDE + lkq],        arow + (size_t)lr * H_DIM + k0_ + lkq);        \
        cp16(&as_[(lr + 64) * A_STRIDE + lkq], arow + (size_t)(lr + 64) * H_DIM + k0_ + lkq); \
        cp16(&bg_[lr * A_STRIDE + lkq],        gte + (size_t)lr * H_DIM + k0_ + lkq);         \
        cp16(&bu_[lr * A_STRIDE + lkq],        ute + (size_t)lr * H_DIM + k0_ + lkq);         \
    } while (0)

    G1_LOAD(0, 0); CP_COMMIT();
    G1_LOAD(1, 1); CP_COMMIT();

    int slot = 0;
    #pragma unroll 1
    for (int ki = 0; ki < NK1; ++ki) {
        CP_WAIT1();
        __syncthreads();
        if (ki + STAGES - 1 < NK1) {
            int ns = slot + 2; if (ns >= STAGES) ns -= STAGES;
            G1_LOAD(ns, ki + STAGES - 1);
        }
        CP_COMMIT();

        const float* as = As + slot * AS_FLOATS;
        const float* bg = Bg + slot * BS_FLOATS;
        const float* bu = Bu + slot * BS_FLOATS;
        #pragma unroll
        for (int ks = 0; ks < 2; ++ks) {
            const int kb = ks * 8 + lt;
            uint32_t af[2][4];
            #pragma unroll
            for (int mt = 0; mt < 2; ++mt) {
                int m = wm * 32 + mt * 16 + lg;
                af[mt][0] = __float_as_uint(as[m * A_STRIDE + kb]);
                af[mt][1] = __float_as_uint(as[(m + 8) * A_STRIDE + kb]);
                af[mt][2] = __float_as_uint(as[m * A_STRIDE + kb + 4]);
                af[mt][3] = __float_as_uint(as[(m + 8) * A_STRIDE + kb + 4]);
            }
            #pragma unroll
            for (int nt = 0; nt < 4; ++nt) {
                int n = wn * 32 + nt * 8 + lg;
                uint32_t bg0 = __float_as_uint(bg[n * A_STRIDE + kb]);
                uint32_t bg1 = __float_as_uint(bg[n * A_STRIDE + kb + 4]);
                uint32_t bu0 = __float_as_uint(bu[n * A_STRIDE + kb]);
                uint32_t bu1 = __float_as_uint(bu[n * A_STRIDE + kb + 4]);
                #pragma unroll
                for (int mt = 0; mt < 2; ++mt) {
                    MMA_TF32(accg[mt][nt], af[mt], bg0, bg1);
                    MMA_TF32(accu[mt][nt], af[mt], bu0, bu1);
                }
            }
        }
        if (++slot == STAGES) slot = 0;
    }
    #undef G1_LOAD

    // epilogue: silu(g)*u -> g_act (tf32)
    #pragma unroll
    for (int mt = 0; mt < 2; ++mt) {
        #pragma unroll
        for (int half = 0; half < 2; ++half) {
            int m = wm * 32 + mt * 16 + lg + half * 8;
            if (m < rows) {
                float* dst = g_act + (size_t)(row0 + m) * I_DIM + n0 + wn * 32;
                #pragma unroll
                for (int nt = 0; nt < 4; ++nt) {
                    float g0 = accg[mt][nt][half * 2 + 0], u0 = accu[mt][nt][half * 2 + 0];
                    float g1 = accg[mt][nt][half * 2 + 1], u1 = accu[mt][nt][half * 2 + 1];
                    float2 o;
                    o.x = to_tf32((g0 / (1.f + __expf(-g0))) * u0);
                    o.y = to_tf32((g1 / (1.f + __expf(-g1))) * u1);
                    *(float2*)(dst + nt * 8 + 2 * lt) = o;
                }
            }
        }
    }
}

// ---------------------------------------------------------------------------
// GEMM2: out[t] += p * (act @ down^T)
// ---------------------------------------------------------------------------
__global__ __launch_bounds__(256, 2)
void k_gemm2_mma(const float* __restrict__ act,
                 const float* __restrict__ dt,
                 float* __restrict__ out) {
    const int tile = blockIdx.x;
    if (tile >= g_num_tiles) return;
    const int e    = g_tile_e[tile];
    const int row0 = g_tile_row0[tile];
    const int rows = g_tile_rows[tile];
    const int n0   = blockIdx.y * BN;

    extern __shared__ float sm[];
    float* As = sm;
    float* Bs = sm + STAGES * AS_FLOATS;

    const int tid  = threadIdx.x;
    const int lane = tid & 31, wid = tid >> 5;
    const int wm = wid & 3, wn = wid >> 2;
    const int lg = lane >> 2, lt = lane & 3;

    const float* arow = act + (size_t)row0 * I_DIM;
    const float* dte  = dt + ((size_t)e * H_DIM + n0) * I_DIM;

    const int lr  = tid >> 2;
    const int lkq = (tid & 3) * 4;

    float acc[2][4][4];
    #pragma unroll
    for (int a = 0; a < 2; ++a)
        #pragma unroll
        for (int b = 0; b < 4; ++b)
            #pragma unroll
            for (int c = 0; c < 4; ++c) acc[a][b][c] = 0.f;

    #define G2_LOAD(s, ki) do {                                                  \
        int k0_ = (ki) * BK;                                                     \
        float* as_ = As + (s) * AS_FLOATS;                                       \
        float* bs_ = Bs + (s) * BS_FLOATS;                                       \
        cp16(&as_[lr * A_STRIDE + lkq],        arow + (size_t)lr * I_DIM + k0_ + lkq);        \
        cp16(&as_[(lr + 64) * A_STRIDE + lkq], arow + (size_t)(lr + 64) * I_DIM + k0_ + lkq); \
        cp16(&bs_[lr * A_STRIDE + lkq],        dte + (size_t)lr * I_DIM + k0_ + lkq);         \
    } while (0)

    G2_LOAD(0, 0); CP_COMMIT();
    G2_LOAD(1, 1); CP_COMMIT();

    int slot = 0;
    #pragma unroll 1
    for (int ki = 0; ki < NK2; ++ki) {
        CP_WAIT1();
        __syncthreads();
        if (ki + STAGES - 1 < NK2) {
            int ns = slot + 2; if (ns >= STAGES) ns -= STAGES;
            G2_LOAD(ns, ki + STAGES - 1);
        }
        CP_COMMIT();

        const float* as = As + slot * AS_FLOATS;
        const float* bs = Bs + slot * BS_FLOATS;
        #pragma unroll
        for (int ks = 0; ks < 2; ++ks) {
            const int kb = ks * 8 + lt;
            uint32_t af[2][4];
            #pragma unroll
            for (int mt = 0; mt < 2; ++mt) {
                int m = wm * 32 + mt * 16 + lg;
                af[mt][0] = __float_as_uint(as[m * A_STRIDE + kb]);
                af[mt][1] = __float_as_uint(as[(m + 8) * A_STRIDE + kb]);
                af[mt][2] = __float_as_uint(as[m * A_STRIDE + kb + 4]);
                af[mt][3] = __float_as_uint(as[(m + 8) * A_STRIDE + kb + 4]);
            }
            #pragma unroll
            for (int nt = 0; nt < 4; ++nt) {
                int n = wn * 32 + nt * 8 + lg;
                uint32_t b0 = __float_as_uint(bs[n * A_STRIDE + kb]);
                uint32_t b1 = __float_as_uint(bs[n * A_STRIDE + kb + 4]);
                #pragma unroll
                for (int mt = 0; mt < 2; ++mt)
                    MMA_TF32(acc[mt][nt], af[mt], b0, b1);
            }
        }
        if (++slot == STAGES) slot = 0;
    }
    #undef G2_LOAD

    // epilogue: weighted scatter-add (each out element gets exactly K=2 adds)
    #pragma unroll
    for (int mt = 0; mt < 2; ++mt) {
        #pragma unroll
        for (int half = 0; half < 2; ++half) {
            int m = wm * 32 + mt * 16 + lg + half * 8;
            if (m < rows) {
                float p = g_row_p[row0 + m];
                int   t = g_row_t[row0 + m];
                float* dst = out + (size_t)t * H_DIM + n0 + wn * 32;
                #pragma unroll
                for (int nt = 0; nt < 4; ++nt) {
                    atomicAdd(dst + nt * 8 + 2 * lt,     acc[mt][nt][half * 2 + 0] * p);
                    atomicAdd(dst + nt * 8 + 2 * lt + 1, acc[mt][nt][half * 2 + 1] * p);
                }
            }
        }
    }
}

// ---------------------------------------------------------------------------
extern "C" void kernel_launch(void* const* d_in, const int* in_sizes, int n_in,
                              void* d_out, int out_size) {
    const float* hid = (const float*)d_in[0];
    const float* rw  = (const float*)d_in[1];
    const int*   sel = (const int*)  d_in[2];
    const float* gw  = (const float*)d_in[3];
    const float* uw  = (const float*)d_in[4];
    const float* dw  = (const float*)d_in[5];
    float* out = (float*)d_out;

    void *p_xp, *p_act, *p_gt, *p_ut, *p_dt;
    cudaGetSymbolAddress(&p_xp,  g_xp);
    cudaGetSymbolAddress(&p_act, g_act);
    cudaGetSymbolAddress(&p_gt,  g_gate_t);
    cudaGetSymbolAddress(&p_ut,  g_up_t);
    cudaGetSymbolAddress(&p_dt,  g_down_t);

    cudaFuncSetAttribute(k_gemm1_mma, cudaFuncAttributeMaxDynamicSharedMemorySize, G1_SMEM);
    cudaFuncSetAttribute(k_gemm2_mma, cudaFuncAttributeMaxDynamicSharedMemorySize, G2_SMEM);

    // routing prep
    k_zero_counts<<<1, 32>>>();
    k_hist<<<R_ROWS / 256, 256>>>(sel);
    k_prep<<<1, 1>>>();
    k_scatter<<<R_ROWS / 256, 256>>>(sel, rw);

    // staging: gather+convert A, transpose+convert weights
    k_permute<<<R_ROWS, 256>>>(hid);
    {
        dim3 b(32, 8);
        dim3 g_gu(I_DIM / 32, H_DIM / 32, N_EXP);   // in [H,I] -> out [I,H]
        k_transpose<H_DIM, I_DIM><<<g_gu, b>>>(gw, (float*)p_gt);
        k_transpose<H_DIM, I_DIM><<<g_gu, b>>>(uw, (float*)p_ut);
        dim3 g_d(H_DIM / 32, I_DIM / 32, N_EXP);    // in [I,H] -> out [H,I]
        k_transpose<I_DIM, H_DIM><<<g_d, b>>>(dw, (float*)p_dt);
    }

    int n4 = (T_TOK * H_DIM) / 4;
    k_zero_out<<<n4 / 256, 256>>>((float4*)out, n4);

    dim3 g1(MAX_TILES, I_DIM / BN);   // 72 x 22
    k_gemm1_mma<<<g1, 256, G1_SMEM>>>((const float*)p_xp, (const float*)p_gt, (const float*)p_ut);

    dim3 g2(MAX_TILES, H_DIM / BN);   // 72 x 32
    k_gemm2_mma<<<g2, 256, G2_SMEM>>>((const float*)p_act, (const float*)p_dt, out);
}

// round 7
// speedup vs baseline: 4.2332x; 1.6769x over previous
#include <cuda_runtime.h>
#include <cuda_fp16.h>
#include <math.h>
#include <stdint.h>

// ---------------------------------------------------------------------------
// MoE grouped MLP via fp16 mma.sync m16n8k16 with static scaling.
// fp16 mantissa == tf32 mantissa (10 bits) -> same accuracy, 2x MAC/inst.
// T=4096 H=2048 I=1408 E=8 K=2; rows = 8192.
// ---------------------------------------------------------------------------
#define T_TOK 4096
#define H_DIM 2048
#define I_DIM 1408
#define N_EXP 8
#define TOPK  2
#define R_ROWS (T_TOK * TOPK)
#define BM 128
#define MAX_TILES (R_ROWS / BM + N_EXP)   // 72

#define BN 64
#define BK 32
#define STAGES 4
#define NK1 (H_DIM / BK)                   // 64
#define NK2 (I_DIM / BK)                   // 44

#define SH 40                              // SMEM row stride in halfs (conflict-free)
#define AS_H (BM * SH)                     // 5120 halfs
#define BS_H (BN * SH)                     // 2560 halfs
#define G1_SMEM ((STAGES * (AS_H + 2 * BS_H)) * 2)   // 81920 B
#define G2_SMEM ((STAGES * (AS_H + BS_H)) * 2)       // 61440 B

#define XP_ROWS  (R_ROWS + 128)
#define ACT_ROWS (R_ROWS + 128)

// static scaling: x*64, W*64, act*4096
#define S_IN   64.0f
#define DESC1  (1.0f / (64.0f * 64.0f))            // after GEMM1
#define S_ACT  4096.0f
#define DESC2  (1.0f / (4096.0f * 64.0f))          // after GEMM2

// ---- device-global scratch ----
__device__ int    g_counts[N_EXP];
__device__ int    g_cursor[N_EXP];
__device__ int    g_tile_e[MAX_TILES];
__device__ int    g_tile_row0[MAX_TILES];
__device__ int    g_tile_rows[MAX_TILES];
__device__ int    g_num_tiles;
__device__ int    g_row_t[R_ROWS];
__device__ float  g_row_p[R_ROWS];
__device__ __half g_xp[(size_t)XP_ROWS * H_DIM];             // scaled fp16 input
__device__ __half g_act[(size_t)ACT_ROWS * I_DIM];           // scaled fp16 activations
__device__ __half g_gate_t[(size_t)N_EXP * I_DIM * H_DIM];   // [E][I][H] col-major B
__device__ __half g_up_t  [(size_t)N_EXP * I_DIM * H_DIM];
__device__ __half g_down_t[(size_t)N_EXP * H_DIM * I_DIM];   // [E][H][I]

// ---------------------------------------------------------------------------
__device__ __forceinline__ void cp16(void* dst, const void* src) {
    uint32_t d = (uint32_t)__cvta_generic_to_shared(dst);
    asm volatile("cp.async.cg.shared.global [%0], [%1], 16;" :: "r"(d), "l"(src) : "memory");
}
#define CP_COMMIT() asm volatile("cp.async.commit_group;" ::: "memory")
#define CP_WAIT2()  asm volatile("cp.async.wait_group 2;" ::: "memory")

// D += A(16x16,row) * B(16x8,col), fp16 in / fp32 accum
#define MMA_F16(d, a, b0, b1)                                                \
    asm volatile("mma.sync.aligned.m16n8k16.row.col.f32.f16.f16.f32 "        \
        "{%0,%1,%2,%3}, {%4,%5,%6,%7}, {%8,%9}, {%0,%1,%2,%3};"              \
        : "+f"((d)[0]), "+f"((d)[1]), "+f"((d)[2]), "+f"((d)[3])             \
        : "r"((a)[0]), "r"((a)[1]), "r"((a)[2]), "r"((a)[3]),                \
          "r"(b0), "r"(b1))

__device__ __forceinline__ uint32_t ldh2(const __half* p) {
    return *(const uint32_t*)p;
}

// ---------------------------------------------------------------------------
// prep kernels
// ---------------------------------------------------------------------------
__global__ void k_zero_counts() { if (threadIdx.x < N_EXP) g_counts[threadIdx.x] = 0; }

__global__ void k_hist(const int* __restrict__ sel) {
    int f = blockIdx.x * blockDim.x + threadIdx.x;
    if (f < R_ROWS) {
        int t = f % T_TOK, k = f / T_TOK;
        atomicAdd(&g_counts[sel[t * TOPK + k]], 1);
    }
}

__global__ void k_prep() {
    int off = 0, nt = 0;
    for (int e = 0; e < N_EXP; ++e) {
        int c = g_counts[e];
        g_cursor[e] = off;
        for (int r0 = 0; r0 < c; r0 += BM) {
            g_tile_e[nt] = e; g_tile_row0[nt] = off + r0;
            g_tile_rows[nt] = min(BM, c - r0); ++nt;
        }
        off += c;
    }
    g_num_tiles = nt;
}

__global__ void k_scatter(const int* __restrict__ sel, const float* __restrict__ rw) {
    int f = blockIdx.x * blockDim.x + threadIdx.x;
    if (f < R_ROWS) {
        int t = f % T_TOK, k = f / T_TOK;
        int e = sel[t * TOPK + k];
        int d = atomicAdd(&g_cursor[e], 1);
        g_row_t[d] = t;
        g_row_p[d] = rw[t * TOPK + k];
    }
}

__global__ void k_zero_out(float4* __restrict__ out, int n4) {
    int i = blockIdx.x * blockDim.x + threadIdx.x;
    if (i < n4) out[i] = make_float4(0.f, 0.f, 0.f, 0.f);
}

// gather rows, scale by 64, convert to fp16
__global__ void k_permute(const float* __restrict__ hid) {
    int r = blockIdx.x;
    int t = g_row_t[r];
    const float4* src = (const float4*)(hid + (size_t)t * H_DIM);
    __half2* dst = (__half2*)(g_xp + (size_t)r * H_DIM);
    for (int i = threadIdx.x; i < H_DIM / 4; i += blockDim.x) {
        float4 v = src[i];
        dst[2*i]   = __floats2half2_rn(v.x * S_IN, v.y * S_IN);
        dst[2*i+1] = __floats2half2_rn(v.z * S_IN, v.w * S_IN);
    }
}

// transpose + scale + fp16 convert: in [R,C] per expert -> out [C,R]
template<int R, int C>
__global__ void k_transpose(const float* __restrict__ in, __half* __restrict__ out) {
    __shared__ float tile[32][33];
    int e = blockIdx.z;
    in  += (size_t)e * R * C;
    out += (size_t)e * R * C;
    int c0 = blockIdx.x * 32, r0 = blockIdx.y * 32;
    int x = threadIdx.x, y = threadIdx.y;
    #pragma unroll
    for (int dy = 0; dy < 32; dy += 8)
        tile[y + dy][x] = in[(size_t)(r0 + y + dy) * C + c0 + x];
    __syncthreads();
    #pragma unroll
    for (int dy = 0; dy < 32; dy += 8)
        out[(size_t)(c0 + y + dy) * R + r0 + x] = __float2half_rn(tile[x][y + dy] * S_IN);
}

// ---------------------------------------------------------------------------
// GEMM1: act = silu(xp @ gate^T) * (xp @ up^T), fp16 mma, 128x64 tiles.
// 256 threads = 8 warps (4M x 2N), warp tile 32x32.
// ---------------------------------------------------------------------------
__global__ __launch_bounds__(256, 2)
void k_gemm1_mma(const __half* __restrict__ xp,
                 const __half* __restrict__ gt,
                 const __half* __restrict__ ut) {
    const int tile = blockIdx.x;
    if (tile >= g_num_tiles) return;
    const int e    = g_tile_e[tile];
    const int row0 = g_tile_row0[tile];
    const int rows = g_tile_rows[tile];
    const int n0   = blockIdx.y * BN;

    extern __shared__ __half sm[];
    __half* As = sm;                          // [S][128][40]
    __half* Bg = sm + STAGES * AS_H;          // [S][64][40]
    __half* Bu = Bg + STAGES * BS_H;

    const int tid  = threadIdx.x;
    const int lane = tid & 31, wid = tid >> 5;
    const int wm = wid & 3, wn = wid >> 2;
    const int lg = lane >> 2, lt = lane & 3;

    const __half* arow = xp + (size_t)row0 * H_DIM;
    const __half* gte  = gt + ((size_t)e * I_DIM + n0) * H_DIM;
    const __half* ute  = ut + ((size_t)e * I_DIM + n0) * H_DIM;

    // loaders: A = 128 rows x 4 chunks (2/thread), B = 64 x 4 (1/thread each)
    const int alr = tid >> 1, alc = (tid & 1) * 2;   // A row, first chunk
    const int blr = tid >> 2, blc = tid & 3;         // B row, chunk

    float accg[2][4][4], accu[2][4][4];
    #pragma unroll
    for (int a = 0; a < 2; ++a)
        #pragma unroll
        for (int b = 0; b < 4; ++b)
            #pragma unroll
            for (int c = 0; c < 4; ++c) { accg[a][b][c] = 0.f; accu[a][b][c] = 0.f; }

    #define G1_LOAD(s, ki) do {                                                   \
        int k0_ = (ki) * BK;                                                      \
        __half* as_ = As + (s) * AS_H;                                            \
        __half* bg_ = Bg + (s) * BS_H;                                            \
        __half* bu_ = Bu + (s) * BS_H;                                            \
        cp16(&as_[alr * SH + alc * 8],       arow + (size_t)alr * H_DIM + k0_ + alc * 8);      \
        cp16(&as_[alr * SH + (alc + 1) * 8], arow + (size_t)alr * H_DIM + k0_ + (alc + 1) * 8);\
        cp16(&bg_[blr * SH + blc * 8],       gte + (size_t)blr * H_DIM + k0_ + blc * 8);       \
        cp16(&bu_[blr * SH + blc * 8],       ute + (size_t)blr * H_DIM + k0_ + blc * 8);       \
    } while (0)

    G1_LOAD(0, 0); CP_COMMIT();
    G1_LOAD(1, 1); CP_COMMIT();
    G1_LOAD(2, 2); CP_COMMIT();

    int slot = 0;
    #pragma unroll 1
    for (int ki = 0; ki < NK1; ++ki) {
        CP_WAIT2();
        __syncthreads();
        if (ki + 3 < NK1) {
            int ns = slot + 3; if (ns >= STAGES) ns -= STAGES;
            G1_LOAD(ns, ki + 3);
        }
        CP_COMMIT();

        const __half* as = As + slot * AS_H;
        const __half* bg = Bg + slot * BS_H;
        const __half* bu = Bu + slot * BS_H;
        #pragma unroll
        for (int ks = 0; ks < 2; ++ks) {
            const int kb = ks * 16 + 2 * lt;
            uint32_t af[2][4];
            #pragma unroll
            for (int mt = 0; mt < 2; ++mt) {
                int m = wm * 32 + mt * 16 + lg;
                af[mt][0] = ldh2(&as[m * SH + kb]);
                af[mt][1] = ldh2(&as[(m + 8) * SH + kb]);
                af[mt][2] = ldh2(&as[m * SH + kb + 8]);
                af[mt][3] = ldh2(&as[(m + 8) * SH + kb + 8]);
            }
            #pragma unroll
            for (int nt = 0; nt < 4; ++nt) {
                int n = wn * 32 + nt * 8 + lg;
                uint32_t bg0 = ldh2(&bg[n * SH + kb]);
                uint32_t bg1 = ldh2(&bg[n * SH + kb + 8]);
                uint32_t bu0 = ldh2(&bu[n * SH + kb]);
                uint32_t bu1 = ldh2(&bu[n * SH + kb + 8]);
                #pragma unroll
                for (int mt = 0; mt < 2; ++mt) {
                    MMA_F16(accg[mt][nt], af[mt], bg0, bg1);
                    MMA_F16(accu[mt][nt], af[mt], bu0, bu1);
                }
            }
        }
        if (++slot == STAGES) slot = 0;
    }
    #undef G1_LOAD

    // epilogue: descale, silu(g)*u, rescale, store fp16
    #pragma unroll
    for (int mt = 0; mt < 2; ++mt) {
        #pragma unroll
        for (int half = 0; half < 2; ++half) {
            int m = wm * 32 + mt * 16 + lg + half * 8;
            if (m < rows) {
                __half* dst = g_act + (size_t)(row0 + m) * I_DIM + n0 + wn * 32;
                #pragma unroll
                for (int nt = 0; nt < 4; ++nt) {
                    float g0 = accg[mt][nt][half * 2 + 0] * DESC1;
                    float u0 = accu[mt][nt][half * 2 + 0] * DESC1;
                    float g1 = accg[mt][nt][half * 2 + 1] * DESC1;
                    float u1 = accu[mt][nt][half * 2 + 1] * DESC1;
                    float a0 = (g0 / (1.f + __expf(-g0))) * u0 * S_ACT;
                    float a1 = (g1 / (1.f + __expf(-g1))) * u1 * S_ACT;
                    *(__half2*)(dst + nt * 8 + 2 * lt) = __floats2half2_rn(a0, a1);
                }
            }
        }
    }
}

// ---------------------------------------------------------------------------
// GEMM2: out[t] += p * descale * (act @ down^T)
// ---------------------------------------------------------------------------
__global__ __launch_bounds__(256, 2)
void k_gemm2_mma(const __half* __restrict__ act,
                 const __half* __restrict__ dt,
                 float* __restrict__ out) {
    const int tile = blockIdx.x;
    if (tile >= g_num_tiles) return;
    const int e    = g_tile_e[tile];
    const int row0 = g_tile_row0[tile];
    const int rows = g_tile_rows[tile];
    const int n0   = blockIdx.y * BN;

    extern __shared__ __half sm[];
    __half* As = sm;
    __half* Bs = sm + STAGES * AS_H;

    const int tid  = threadIdx.x;
    const int lane = tid & 31, wid = tid >> 5;
    const int wm = wid & 3, wn = wid >> 2;
    const int lg = lane >> 2, lt = lane & 3;

    const __half* arow = act + (size_t)row0 * I_DIM;
    const __half* dte  = dt + ((size_t)e * H_DIM + n0) * I_DIM;

    const int alr = tid >> 1, alc = (tid & 1) * 2;
    const int blr = tid >> 2, blc = tid & 3;

    float acc[2][4][4];
    #pragma unroll
    for (int a = 0; a < 2; ++a)
        #pragma unroll
        for (int b = 0; b < 4; ++b)
            #pragma unroll
            for (int c = 0; c < 4; ++c) acc[a][b][c] = 0.f;

    #define G2_LOAD(s, ki) do {                                                   \
        int k0_ = (ki) * BK;                                                      \
        __half* as_ = As + (s) * AS_H;                                            \
        __half* bs_ = Bs + (s) * BS_H;                                            \
        cp16(&as_[alr * SH + alc * 8],       arow + (size_t)alr * I_DIM + k0_ + alc * 8);      \
        cp16(&as_[alr * SH + (alc + 1) * 8], arow + (size_t)alr * I_DIM + k0_ + (alc + 1) * 8);\
        cp16(&bs_[blr * SH + blc * 8],       dte + (size_t)blr * I_DIM + k0_ + blc * 8);       \
    } while (0)

    G2_LOAD(0, 0); CP_COMMIT();
    G2_LOAD(1, 1); CP_COMMIT();
    G2_LOAD(2, 2); CP_COMMIT();

    int slot = 0;
    #pragma unroll 1
    for (int ki = 0; ki < NK2; ++ki) {
        CP_WAIT2();
        __syncthreads();
        if (ki + 3 < NK2) {
            int ns = slot + 3; if (ns >= STAGES) ns -= STAGES;
            G2_LOAD(ns, ki + 3);
        }
        CP_COMMIT();

        const __half* as = As + slot * AS_H;
        const __half* bs = Bs + slot * BS_H;
        #pragma unroll
        for (int ks = 0; ks < 2; ++ks) {
            const int kb = ks * 16 + 2 * lt;
            uint32_t af[2][4];
            #pragma unroll
            for (int mt = 0; mt < 2; ++mt) {
                int m = wm * 32 + mt * 16 + lg;
                af[mt][0] = ldh2(&as[m * SH + kb]);
                af[mt][1] = ldh2(&as[(m + 8) * SH + kb]);
                af[mt][2] = ldh2(&as[m * SH + kb + 8]);
                af[mt][3] = ldh2(&as[(m + 8) * SH + kb + 8]);
            }
            #pragma unroll
            for (int nt = 0; nt < 4; ++nt) {
                int n = wn * 32 + nt * 8 + lg;
                uint32_t b0 = ldh2(&bs[n * SH + kb]);
                uint32_t b1 = ldh2(&bs[n * SH + kb + 8]);
                #pragma unroll
                for (int mt = 0; mt < 2; ++mt)
                    MMA_F16(acc[mt][nt], af[mt], b0, b1);
            }
        }
        if (++slot == STAGES) slot = 0;
    }
    #undef G2_LOAD

    // epilogue: weighted scatter-add with descale
    #pragma unroll
    for (int mt = 0; mt < 2; ++mt) {
        #pragma unroll
        for (int half = 0; half < 2; ++half) {
            int m = wm * 32 + mt * 16 + lg + half * 8;
            if (m < rows) {
                float p = g_row_p[row0 + m] * DESC2;
                int   t = g_row_t[row0 + m];
                float* dst = out + (size_t)t * H_DIM + n0 + wn * 32;
                #pragma unroll
                for (int nt = 0; nt < 4; ++nt) {
                    atomicAdd(dst + nt * 8 + 2 * lt,     acc[mt][nt][half * 2 + 0] * p);
                    atomicAdd(dst + nt * 8 + 2 * lt + 1, acc[mt][nt][half * 2 + 1] * p);
                }
            }
        }
    }
}

// ---------------------------------------------------------------------------
extern "C" void kernel_launch(void* const* d_in, const int* in_sizes, int n_in,
                              void* d_out, int out_size) {
    const float* hid = (const float*)d_in[0];
    const float* rw  = (const float*)d_in[1];
    const int*   sel = (const int*)  d_in[2];
    const float* gw  = (const float*)d_in[3];
    const float* uw  = (const float*)d_in[4];
    const float* dw  = (const float*)d_in[5];
    float* out = (float*)d_out;

    void *p_xp, *p_act, *p_gt, *p_ut, *p_dt;
    cudaGetSymbolAddress(&p_xp,  g_xp);
    cudaGetSymbolAddress(&p_act, g_act);
    cudaGetSymbolAddress(&p_gt,  g_gate_t);
    cudaGetSymbolAddress(&p_ut,  g_up_t);
    cudaGetSymbolAddress(&p_dt,  g_down_t);

    cudaFuncSetAttribute(k_gemm1_mma, cudaFuncAttributeMaxDynamicSharedMemorySize, G1_SMEM);
    cudaFuncSetAttribute(k_gemm2_mma, cudaFuncAttributeMaxDynamicSharedMemorySize, G2_SMEM);

    // routing prep
    k_zero_counts<<<1, 32>>>();
    k_hist<<<R_ROWS / 256, 256>>>(sel);
    k_prep<<<1, 1>>>();
    k_scatter<<<R_ROWS / 256, 256>>>(sel, rw);

    // staging: gather+scale+fp16 A, transpose+scale+fp16 weights
    k_permute<<<R_ROWS, 256>>>(hid);
    {
        dim3 b(32, 8);
        dim3 g_gu(I_DIM / 32, H_DIM / 32, N_EXP);   // [H,I] -> [I,H]
        k_transpose<H_DIM, I_DIM><<<g_gu, b>>>(gw, (__half*)p_gt);
        k_transpose<H_DIM, I_DIM><<<g_gu, b>>>(uw, (__half*)p_ut);
        dim3 g_d(H_DIM / 32, I_DIM / 32, N_EXP);    // [I,H] -> [H,I]
        k_transpose<I_DIM, H_DIM><<<g_d, b>>>(dw, (__half*)p_dt);
    }

    int n4 = (T_TOK * H_DIM) / 4;
    k_zero_out<<<n4 / 256, 256>>>((float4*)out, n4);

    dim3 g1(MAX_TILES, I_DIM / BN);   // 72 x 22
    k_gemm1_mma<<<g1, 256, G1_SMEM>>>((const __half*)p_xp, (const __half*)p_gt, (const __half*)p_ut);

    dim3 g2(MAX_TILES, H_DIM / BN);   // 72 x 32
    k_gemm2_mma<<<g2, 256, G2_SMEM>>>((const __half*)p_act, (const __half*)p_dt, out);
}